// round 9
// baseline (speedup 1.0000x reference)
#include <cuda_runtime.h>
#include <cuda_bf16.h>
#include <cstdint>
#include <cstddef>

#define T_DIM 4096
#define C_DIM 1024
#define D_DIM 256
#define VOCAB 32000

// Shared tile row stride (bf16): 32 data + 8 pad = 40 (80B rows = 5*16B,
// uint4-aligned; ldmatrix phases conflict-free: row r -> word (r*20)%32 =
// {0,20,8,28,16,4,24,12}, distinct 16B bank groups).
#define SMPAD 40
#define STAGES 3

// ---------------- scratch (__device__ globals: allocation-free rule) --------
__device__ __nv_bfloat16 g_x_hi[T_DIM * C_DIM];
__device__ __nv_bfloat16 g_x_lo[T_DIM * C_DIM];
__device__ __nv_bfloat16 g_wt_hi[2][D_DIM * C_DIM];   // W^T [n][k], 0=Wq 1=Wk
__device__ __nv_bfloat16 g_wt_lo[2][D_DIM * C_DIM];
__device__ __nv_bfloat16 g_q_hi[T_DIM * D_DIM];
__device__ __nv_bfloat16 g_q_lo[T_DIM * D_DIM];
__device__ __nv_bfloat16 g_k_hi[T_DIM * D_DIM];
__device__ __nv_bfloat16 g_k_lo[T_DIM * D_DIM];
__device__ float g_c[(size_t)T_DIM * T_DIM];          // lower-tri only
__device__ int   g_idx[T_DIM];

// ---------------------------------------------------------------------------
__global__ void idx_convert_kernel(const int* __restrict__ raw) {
    __shared__ int is64;
    int tid = threadIdx.x;
    if (tid == 0) is64 = 1;
    __syncthreads();
    for (int i = tid; i < 1024; i += blockDim.x)
        if (raw[2 * i + 1] != 0) is64 = 0;
    __syncthreads();
    bool i64 = (is64 != 0);
    for (int i = tid; i < T_DIM; i += blockDim.x)
        g_idx[i] = i64 ? raw[2 * i] : raw[i];
}

__device__ __forceinline__ void split2(float v, __nv_bfloat16& h, __nv_bfloat16& l) {
    h = __float2bfloat16(v);
    l = __float2bfloat16(v - __bfloat162float(h));
}

__global__ void split_x_kernel(const float* __restrict__ x) {
    const int n4 = T_DIM * C_DIM / 4;
    __nv_bfloat162* H = reinterpret_cast<__nv_bfloat162*>(g_x_hi);
    __nv_bfloat162* L = reinterpret_cast<__nv_bfloat162*>(g_x_lo);
    for (int i = blockIdx.x * blockDim.x + threadIdx.x; i < n4;
         i += gridDim.x * blockDim.x) {
        float4 v = reinterpret_cast<const float4*>(x)[i];
        __nv_bfloat16 h0, h1, h2, h3, l0, l1, l2, l3;
        split2(v.x, h0, l0); split2(v.y, h1, l1);
        split2(v.z, h2, l2); split2(v.w, h3, l3);
        H[2 * i]     = __halves2bfloat162(h0, h1);
        H[2 * i + 1] = __halves2bfloat162(h2, h3);
        L[2 * i]     = __halves2bfloat162(l0, l1);
        L[2 * i + 1] = __halves2bfloat162(l2, l3);
    }
}

__global__ void split_w_kernel(const float* __restrict__ Wq,
                               const float* __restrict__ Wk) {
    const float* W = blockIdx.y ? Wk : Wq;
    __nv_bfloat16* hi = g_wt_hi[blockIdx.y];
    __nv_bfloat16* lo = g_wt_lo[blockIdx.y];
    const int total = D_DIM * C_DIM;
    for (int i = blockIdx.x * blockDim.x + threadIdx.x; i < total;
         i += gridDim.x * blockDim.x) {
        int n = i / C_DIM, k = i % C_DIM;
        split2(W[(size_t)k * D_DIM + n], hi[i], lo[i]);
    }
}

// ---------------------------------------------------------------------------
__device__ __forceinline__ void mma16816(float* d, const uint32_t* a,
                                         const uint32_t* b) {
    asm volatile(
        "mma.sync.aligned.m16n8k16.row.col.f32.bf16.bf16.f32 "
        "{%0,%1,%2,%3},{%4,%5,%6,%7},{%8,%9},{%0,%1,%2,%3};"
        : "+f"(d[0]), "+f"(d[1]), "+f"(d[2]), "+f"(d[3])
        : "r"(a[0]), "r"(a[1]), "r"(a[2]), "r"(a[3]), "r"(b[0]), "r"(b[1]));
}

__device__ __forceinline__ uint32_t smem_u32(const void* p) {
    return (uint32_t)__cvta_generic_to_shared(p);
}
__device__ __forceinline__ void ldsm4(uint32_t* r, const void* p) {
    asm volatile("ldmatrix.sync.aligned.m8n8.x4.shared.b16 {%0,%1,%2,%3}, [%4];"
                 : "=r"(r[0]), "=r"(r[1]), "=r"(r[2]), "=r"(r[3])
                 : "r"(smem_u32(p)));
}

__device__ __forceinline__ void cp16(void* smem, const void* gmem) {
    asm volatile("cp.async.cg.shared.global [%0], [%1], 16;"
                 :: "r"(smem_u32(smem)), "l"(gmem));
}
__device__ __forceinline__ void cp_commit() {
    asm volatile("cp.async.commit_group;");
}
template <int N>
__device__ __forceinline__ void cp_wait() {
    asm volatile("cp.async.wait_group %0;" :: "n"(N));
}

// One pipeline stage: 30720 B
struct Tiles {
    __nv_bfloat16 As_hi[128][SMPAD];
    __nv_bfloat16 As_lo[128][SMPAD];
    __nv_bfloat16 Bs_hi[64][SMPAD];
    __nv_bfloat16 Bs_lo[64][SMPAD];
};

// Compute one BK=32 slab. 8 warps (4x2), warp tile 32x32, split-bf16 3-term.
// ALL fragments for the slab (both k16 halves, A+B, hi+lo: 16 LDSM) are
// preloaded before any HMMA issues -> one 48-deep HMMA burst per warp per
// slab, fully covering LDSM latency instead of stalling per k16 half.
__device__ __forceinline__ void compute_slab(const Tiles& st, int wm, int wn,
                                             int lane, float acc[2][4][4]) {
    const int ra = (lane & 7) + ((lane >> 3) & 1) * 8;  // A: row within m16
    const int ca = (lane >> 4) * 8;                     // A: k-half select
    const int rb = (lane & 7) + (lane >> 4) * 8;        // B: row within n16
    const int cb = ((lane >> 3) & 1) * 8;               // B: k-half select

    uint32_t ah[2][2][4], al[2][2][4], bh[2][4][2], bl[2][4][2];

    #pragma unroll
    for (int h = 0; h < 2; h++) {
        const int s16 = h * 16;
        #pragma unroll
        for (int ms = 0; ms < 2; ms++) {
            int r = wm * 32 + ms * 16 + ra;
            ldsm4(ah[h][ms], &st.As_hi[r][s16 + ca]);
            ldsm4(al[h][ms], &st.As_lo[r][s16 + ca]);
        }
        #pragma unroll
        for (int pr = 0; pr < 2; pr++) {
            int r = wn * 32 + pr * 16 + rb;
            uint32_t q[4];
            ldsm4(q, &st.Bs_hi[r][s16 + cb]);
            bh[h][2 * pr][0] = q[0]; bh[h][2 * pr][1] = q[1];
            bh[h][2 * pr + 1][0] = q[2]; bh[h][2 * pr + 1][1] = q[3];
            ldsm4(q, &st.Bs_lo[r][s16 + cb]);
            bl[h][2 * pr][0] = q[0]; bl[h][2 * pr][1] = q[1];
            bl[h][2 * pr + 1][0] = q[2]; bl[h][2 * pr + 1][1] = q[3];
        }
    }

    #pragma unroll
    for (int h = 0; h < 2; h++) {
        #pragma unroll
        for (int ms = 0; ms < 2; ms++)
            #pragma unroll
            for (int ns = 0; ns < 4; ns++)
                mma16816(acc[ms][ns], ah[h][ms], bh[h][ns]);
        #pragma unroll
        for (int ms = 0; ms < 2; ms++)
            #pragma unroll
            for (int ns = 0; ns < 4; ns++)
                mma16816(acc[ms][ns], ah[h][ms], bl[h][ns]);
        #pragma unroll
        for (int ms = 0; ms < 2; ms++)
            #pragma unroll
            for (int ns = 0; ns < 4; ns++)
                mma16816(acc[ms][ns], al[h][ms], bh[h][ns]);
    }
}

// Async-load one slab and commit one group.
__device__ __forceinline__ void load_slab(Tiles& st, int tid,
                                          const __nv_bfloat16* aH,
                                          const __nv_bfloat16* aL, size_t ldA,
                                          const __nv_bfloat16* bH,
                                          const __nv_bfloat16* bL, size_t ldB,
                                          int k0) {
    #pragma unroll
    for (int s = 0; s < 2; s++) {
        int idx = tid + s * 256;
        int r = idx >> 2, cw = (idx & 3) * 8;
        size_t go = (size_t)r * ldA + k0 + cw;
        cp16(&st.As_hi[r][cw], &aH[go]);
        cp16(&st.As_lo[r][cw], &aL[go]);
    }
    {
        int r = tid >> 2, cw = (tid & 3) * 8;
        size_t go = (size_t)r * ldB + k0 + cw;
        cp16(&st.Bs_hi[r][cw], &bH[go]);
        cp16(&st.Bs_lo[r][cw], &bL[go]);
    }
    cp_commit();
}

// 3-stage, single-sync-per-slab mainloop.
template <int KT>
__device__ __forceinline__ void gemm_mainloop(
    Tiles* stages, int tid, int wm, int wn, int lane,
    const __nv_bfloat16* aH, const __nv_bfloat16* aL, size_t ldA,
    const __nv_bfloat16* bH, const __nv_bfloat16* bL, size_t ldB,
    float acc[2][4][4]) {

    load_slab(stages[0], tid, aH, aL, ldA, bH, bL, ldB, 0);
    if (KT > 1) load_slab(stages[1], tid, aH, aL, ldA, bH, bL, ldB, 32);

    for (int i = 0; i < KT; i++) {
        cp_wait<1>();          // stage i complete (newest pending may be i+1)
        __syncthreads();       // all warps done with stage (i-1) -> reusable
        int nx = i + STAGES - 1;
        if (nx < KT)
            load_slab(stages[nx % STAGES], tid, aH, aL, ldA, bH, bL, ldB, nx * 32);
        else
            cp_commit();       // keep group count uniform
        compute_slab(stages[i % STAGES], wm, wn, lane, acc);
    }
}

// ---------------------------------------------------------------------------
// qk GEMM: q/k = x @ W. BM=128 BN=64 BK=32, K=1024 (32 slabs).
// ---------------------------------------------------------------------------
__global__ __launch_bounds__(256, 2) void qk_mma_kernel() {
    extern __shared__ Tiles stages[];   // [STAGES]

    const int z = blockIdx.z;
    const int m0 = blockIdx.y * 128;
    const int n0 = blockIdx.x * 64;

    const int tid  = threadIdx.x;
    const int warp = tid >> 5, lane = tid & 31;
    const int wm = warp >> 1, wn = warp & 1;
    const int g = lane >> 2, tg = lane & 3;

    float acc[2][4][4] = {};
    gemm_mainloop<C_DIM / 32>(
        stages, tid, wm, wn, lane,
        g_x_hi + (size_t)m0 * C_DIM, g_x_lo + (size_t)m0 * C_DIM, C_DIM,
        g_wt_hi[z] + (size_t)n0 * C_DIM, g_wt_lo[z] + (size_t)n0 * C_DIM, C_DIM,
        acc);

    __nv_bfloat16* dh = z ? g_k_hi : g_q_hi;
    __nv_bfloat16* dl = z ? g_k_lo : g_q_lo;
    #pragma unroll
    for (int ms = 0; ms < 2; ms++)
        #pragma unroll
        for (int ns = 0; ns < 4; ns++) {
            int m = m0 + wm * 32 + ms * 16 + g;
            int n = n0 + wn * 32 + ns * 8 + tg * 2;
            float* c = acc[ms][ns];
            __nv_bfloat16 h0, h1, l0, l1;
            split2(c[0], h0, l0); split2(c[1], h1, l1);
            *reinterpret_cast<__nv_bfloat162*>(&dh[(size_t)m * D_DIM + n]) =
                __halves2bfloat162(h0, h1);
            *reinterpret_cast<__nv_bfloat162*>(&dl[(size_t)m * D_DIM + n]) =
                __halves2bfloat162(l0, l1);
            split2(c[2], h0, l0); split2(c[3], h1, l1);
            *reinterpret_cast<__nv_bfloat162*>(&dh[(size_t)(m + 8) * D_DIM + n]) =
                __halves2bfloat162(h0, h1);
            *reinterpret_cast<__nv_bfloat162*>(&dl[(size_t)(m + 8) * D_DIM + n]) =
                __halves2bfloat162(l0, l1);
        }
}

// ---------------------------------------------------------------------------
// c GEMM: c = (q @ k^T)/256, triangular grid of 1056 live tiles.
// ---------------------------------------------------------------------------
__global__ __launch_bounds__(256, 2) void c_mma_kernel() {
    extern __shared__ Tiles stages[];   // [STAGES]

    const int bid = blockIdx.x;
    int by = (int)((sqrtf(4.0f * bid + 1.0f) - 1.0f) * 0.5f);
    while (by * by + by > bid) by--;
    while ((by + 1) * (by + 1) + (by + 1) <= bid) by++;
    const int bx = bid - (by * by + by);

    const int t0 = by * 128;
    const int j0 = bx * 64;

    const int tid  = threadIdx.x;
    const int warp = tid >> 5, lane = tid & 31;
    const int wm = warp >> 1, wn = warp & 1;
    const int g = lane >> 2, tg = lane & 3;

    float acc[2][4][4] = {};
    gemm_mainloop<D_DIM / 32>(
        stages, tid, wm, wn, lane,
        g_q_hi + (size_t)t0 * D_DIM, g_q_lo + (size_t)t0 * D_DIM, D_DIM,
        g_k_hi + (size_t)j0 * D_DIM, g_k_lo + (size_t)j0 * D_DIM, D_DIM,
        acc);

    const float scale = 1.0f / 256.0f;
    #pragma unroll
    for (int ms = 0; ms < 2; ms++)
        #pragma unroll
        for (int ns = 0; ns < 4; ns++) {
            int m = t0 + wm * 32 + ms * 16 + g;
            int n = j0 + wn * 32 + ns * 8 + tg * 2;
            float* c = acc[ms][ns];
            *reinterpret_cast<float2*>(&g_c[(size_t)m * T_DIM + n]) =
                make_float2(c[0] * scale, c[1] * scale);
            *reinterpret_cast<float2*>(&g_c[(size_t)(m + 8) * T_DIM + n]) =
                make_float2(c[2] * scale, c[3] * scale);
        }
}

// ---------------------------------------------------------------------------
// scatter: each CTA owns (row t, vocab quarter). 32KB hist -> 4 CTAs/SM,
// 2048 threads/SM; zero/atomic/write phases of co-resident CTAs overlap so
// the 524MB output stream stays saturated.
// ---------------------------------------------------------------------------
#define QUART_V (VOCAB / 4)

__global__ __launch_bounds__(512) void scatter_kernel(float* __restrict__ out) {
    extern __shared__ float hist[];  // QUART_V floats = 32000 B
    const int t    = blockIdx.x >> 2;
    const int qi   = blockIdx.x & 3;
    const int vlo  = qi * QUART_V;
    const int tid = threadIdx.x;
    const int nt = blockDim.x;

    float4* h4 = reinterpret_cast<float4*>(hist);
    const float4 z4 = make_float4(0.f, 0.f, 0.f, 0.f);
    for (int i = tid; i < QUART_V / 4; i += nt) h4[i] = z4;
    __syncthreads();

    const float* crow = &g_c[(size_t)t * T_DIM];
    for (int j = tid; j <= t; j += nt) {
        unsigned v = (unsigned)(g_idx[j] - vlo);
        if (v < (unsigned)QUART_V) atomicAdd(&hist[v], crow[j]);
    }
    __syncthreads();

    float4* o4 = reinterpret_cast<float4*>(out + (size_t)t * VOCAB + vlo);
    for (int i = tid; i < QUART_V / 4; i += nt) __stcs(&o4[i], h4[i]);
}

// ---------------------------------------------------------------------------
extern "C" void kernel_launch(void* const* d_in, const int* in_sizes, int n_in,
                              void* d_out, int out_size) {
    const float* x      = (const float*)d_in[0];
    const int*   idxraw = (const int*)d_in[1];
    const float* Wq     = (const float*)d_in[2];
    const float* Wk     = (const float*)d_in[3];
    float*       out    = (float*)d_out;
    (void)in_sizes; (void)n_in; (void)out_size;

    const int PIPE_SMEM = STAGES * (int)sizeof(Tiles);   // 92160 B

    idx_convert_kernel<<<1, 256>>>(idxraw);
    split_x_kernel<<<1024, 256>>>(x);
    split_w_kernel<<<dim3(64, 2), 256>>>(Wq, Wk);

    cudaFuncSetAttribute(qk_mma_kernel,
                         cudaFuncAttributeMaxDynamicSharedMemorySize, PIPE_SMEM);
    qk_mma_kernel<<<dim3(4, 32, 2), 256, PIPE_SMEM>>>();

    cudaFuncSetAttribute(c_mma_kernel,
                         cudaFuncAttributeMaxDynamicSharedMemorySize, PIPE_SMEM);
    c_mma_kernel<<<1056, 256, PIPE_SMEM>>>();

    cudaFuncSetAttribute(scatter_kernel,
                         cudaFuncAttributeMaxDynamicSharedMemorySize,
                         QUART_V * (int)sizeof(float));
    scatter_kernel<<<4 * T_DIM, 512, QUART_V * sizeof(float)>>>(out);
}

// round 10
// speedup vs baseline: 1.2768x; 1.2768x over previous
#include <cuda_runtime.h>
#include <cuda_fp16.h>
#include <cstdint>
#include <cstddef>

#define T_DIM 4096
#define C_DIM 1024
#define D_DIM 256
#define VOCAB 32000

// Shared tile row stride (fp16): 32 data + 8 pad = 40 (80B rows = 5*16B,
// uint4-aligned; ldmatrix phases conflict-free: row r -> word (r*20)%32 =
// {0,20,8,28,16,4,24,12}, distinct 16B bank groups).
#define SMPAD 40
#define STAGES 3

// ---------------- scratch (__device__ globals: allocation-free rule) --------
// 2-term split-fp16 scheme: A operands stored hi-only, B operands hi+lo.
__device__ __half g_x_h[T_DIM * C_DIM];               // x hi (A of qk)
__device__ __half g_wt_h[2][D_DIM * C_DIM];           // W^T hi (B of qk)
__device__ __half g_wt_l[2][D_DIM * C_DIM];           // W^T lo
__device__ __half g_q_h[T_DIM * D_DIM];               // q hi (A of c)
__device__ __half g_k_h[T_DIM * D_DIM];               // k hi (B of c)
__device__ __half g_k_l[T_DIM * D_DIM];               // k lo
__device__ float g_c[(size_t)T_DIM * T_DIM];          // lower-tri only
__device__ int   g_idx[T_DIM];

// ---------------------------------------------------------------------------
__global__ void idx_convert_kernel(const int* __restrict__ raw) {
    __shared__ int is64;
    int tid = threadIdx.x;
    if (tid == 0) is64 = 1;
    __syncthreads();
    for (int i = tid; i < 1024; i += blockDim.x)
        if (raw[2 * i + 1] != 0) is64 = 0;
    __syncthreads();
    bool i64 = (is64 != 0);
    for (int i = tid; i < T_DIM; i += blockDim.x)
        g_idx[i] = i64 ? raw[2 * i] : raw[i];
}

__device__ __forceinline__ void split2h(float v, __half& h, __half& l) {
    h = __float2half_rn(v);
    l = __float2half_rn(v - __half2float(h));
}

__global__ void split_x_kernel(const float* __restrict__ x) {
    const int n4 = T_DIM * C_DIM / 4;
    __half2* H = reinterpret_cast<__half2*>(g_x_h);
    for (int i = blockIdx.x * blockDim.x + threadIdx.x; i < n4;
         i += gridDim.x * blockDim.x) {
        float4 v = reinterpret_cast<const float4*>(x)[i];
        H[2 * i]     = __floats2half2_rn(v.x, v.y);
        H[2 * i + 1] = __floats2half2_rn(v.z, v.w);
    }
}

__global__ void split_w_kernel(const float* __restrict__ Wq,
                               const float* __restrict__ Wk) {
    const float* W = blockIdx.y ? Wk : Wq;
    __half* hi = g_wt_h[blockIdx.y];
    __half* lo = g_wt_l[blockIdx.y];
    const int total = D_DIM * C_DIM;
    for (int i = blockIdx.x * blockDim.x + threadIdx.x; i < total;
         i += gridDim.x * blockDim.x) {
        int n = i / C_DIM, k = i % C_DIM;
        split2h(W[(size_t)k * D_DIM + n], hi[i], lo[i]);  // store transposed
    }
}

// ---------------------------------------------------------------------------
__device__ __forceinline__ void mma16816(float* d, const uint32_t* a,
                                         const uint32_t* b) {
    asm volatile(
        "mma.sync.aligned.m16n8k16.row.col.f32.f16.f16.f32 "
        "{%0,%1,%2,%3},{%4,%5,%6,%7},{%8,%9},{%0,%1,%2,%3};"
        : "+f"(d[0]), "+f"(d[1]), "+f"(d[2]), "+f"(d[3])
        : "r"(a[0]), "r"(a[1]), "r"(a[2]), "r"(a[3]), "r"(b[0]), "r"(b[1]));
}

__device__ __forceinline__ uint32_t smem_u32(const void* p) {
    return (uint32_t)__cvta_generic_to_shared(p);
}
__device__ __forceinline__ void ldsm4(uint32_t* r, const void* p) {
    asm volatile("ldmatrix.sync.aligned.m8n8.x4.shared.b16 {%0,%1,%2,%3}, [%4];"
                 : "=r"(r[0]), "=r"(r[1]), "=r"(r[2]), "=r"(r[3])
                 : "r"(smem_u32(p)));
}

__device__ __forceinline__ void cp16(void* smem, const void* gmem) {
    asm volatile("cp.async.cg.shared.global [%0], [%1], 16;"
                 :: "r"(smem_u32(smem)), "l"(gmem));
}
__device__ __forceinline__ void cp_commit() {
    asm volatile("cp.async.commit_group;");
}
template <int N>
__device__ __forceinline__ void cp_wait() {
    asm volatile("cp.async.wait_group %0;" :: "n"(N));
}

// One pipeline stage: 20480 B (A hi 10240, B hi 5120, B lo 5120)
struct Tiles {
    __half As_h[128][SMPAD];
    __half Bs_h[64][SMPAD];
    __half Bs_l[64][SMPAD];
};

// Compute one BK=32 slab. 8 warps (4x2), warp tile 32x32, 2-term split-fp16:
// acc += Ah*Bh + Ah*Bl. Per half: 6 LDSM.x4 -> 16 HMMA; 12 LDSM + 32 HMMA/slab.
__device__ __forceinline__ void compute_slab(const Tiles& st, int wm, int wn,
                                             int lane, float acc[2][4][4]) {
    const int ra = (lane & 7) + ((lane >> 3) & 1) * 8;  // A: row within m16
    const int ca = (lane >> 4) * 8;                     // A: k-half select
    const int rb = (lane & 7) + (lane >> 4) * 8;        // B: row within n16
    const int cb = ((lane >> 3) & 1) * 8;               // B: k-half select

    #pragma unroll
    for (int h = 0; h < 2; h++) {
        const int s16 = h * 16;
        uint32_t ah[2][4], bh[4][2], bl[4][2];
        #pragma unroll
        for (int ms = 0; ms < 2; ms++) {
            int r = wm * 32 + ms * 16 + ra;
            ldsm4(ah[ms], &st.As_h[r][s16 + ca]);
        }
        #pragma unroll
        for (int pr = 0; pr < 2; pr++) {
            int r = wn * 32 + pr * 16 + rb;
            uint32_t q[4];
            ldsm4(q, &st.Bs_h[r][s16 + cb]);
            bh[2 * pr][0] = q[0]; bh[2 * pr][1] = q[1];
            bh[2 * pr + 1][0] = q[2]; bh[2 * pr + 1][1] = q[3];
            ldsm4(q, &st.Bs_l[r][s16 + cb]);
            bl[2 * pr][0] = q[0]; bl[2 * pr][1] = q[1];
            bl[2 * pr + 1][0] = q[2]; bl[2 * pr + 1][1] = q[3];
        }
        #pragma unroll
        for (int ms = 0; ms < 2; ms++)
            #pragma unroll
            for (int ns = 0; ns < 4; ns++)
                mma16816(acc[ms][ns], ah[ms], bh[ns]);
        #pragma unroll
        for (int ms = 0; ms < 2; ms++)
            #pragma unroll
            for (int ns = 0; ns < 4; ns++)
                mma16816(acc[ms][ns], ah[ms], bl[ns]);
    }
}

// Async-load one slab and commit one group (4 cp16 per thread).
__device__ __forceinline__ void load_slab(Tiles& st, int tid,
                                          const __half* a, size_t ldA,
                                          const __half* bH, const __half* bL,
                                          size_t ldB, int k0) {
    #pragma unroll
    for (int s = 0; s < 2; s++) {
        int idx = tid + s * 256;
        int r = idx >> 2, cw = (idx & 3) * 8;
        cp16(&st.As_h[r][cw], &a[(size_t)r * ldA + k0 + cw]);
    }
    {
        int r = tid >> 2, cw = (tid & 3) * 8;
        size_t go = (size_t)r * ldB + k0 + cw;
        cp16(&st.Bs_h[r][cw], &bH[go]);
        cp16(&st.Bs_l[r][cw], &bL[go]);
    }
    cp_commit();
}

// 3-stage, single-sync-per-slab mainloop.
template <int KT>
__device__ __forceinline__ void gemm_mainloop(
    Tiles* stages, int tid, int wm, int wn, int lane,
    const __half* a, size_t ldA,
    const __half* bH, const __half* bL, size_t ldB,
    float acc[2][4][4]) {

    load_slab(stages[0], tid, a, ldA, bH, bL, ldB, 0);
    if (KT > 1) load_slab(stages[1], tid, a, ldA, bH, bL, ldB, 32);

    for (int i = 0; i < KT; i++) {
        cp_wait<1>();          // stage i complete (newest pending may be i+1)
        __syncthreads();       // all warps done with stage (i-1) -> reusable
        int nx = i + STAGES - 1;
        if (nx < KT)
            load_slab(stages[nx % STAGES], tid, a, ldA, bH, bL, ldB, nx * 32);
        else
            cp_commit();       // keep group count uniform
        compute_slab(stages[i % STAGES], wm, wn, lane, acc);
    }
}

// ---------------------------------------------------------------------------
// qk GEMM: q/k = x @ W (2-term fp16). BM=128 BN=64 BK=32, K=1024.
// z=0 -> q (store hi only); z=1 -> k (store hi+lo).
// ---------------------------------------------------------------------------
__global__ __launch_bounds__(256, 3) void qk_mma_kernel() {
    extern __shared__ Tiles stages[];   // [STAGES]

    const int z = blockIdx.z;
    const int m0 = blockIdx.y * 128;
    const int n0 = blockIdx.x * 64;

    const int tid  = threadIdx.x;
    const int warp = tid >> 5, lane = tid & 31;
    const int wm = warp >> 1, wn = warp & 1;
    const int g = lane >> 2, tg = lane & 3;

    float acc[2][4][4] = {};
    gemm_mainloop<C_DIM / 32>(
        stages, tid, wm, wn, lane,
        g_x_h + (size_t)m0 * C_DIM, C_DIM,
        g_wt_h[z] + (size_t)n0 * C_DIM, g_wt_l[z] + (size_t)n0 * C_DIM, C_DIM,
        acc);

    #pragma unroll
    for (int ms = 0; ms < 2; ms++)
        #pragma unroll
        for (int ns = 0; ns < 4; ns++) {
            int m = m0 + wm * 32 + ms * 16 + g;
            int n = n0 + wn * 32 + ns * 8 + tg * 2;
            float* c = acc[ms][ns];
            if (z == 0) {
                *reinterpret_cast<__half2*>(&g_q_h[(size_t)m * D_DIM + n]) =
                    __floats2half2_rn(c[0], c[1]);
                *reinterpret_cast<__half2*>(&g_q_h[(size_t)(m + 8) * D_DIM + n]) =
                    __floats2half2_rn(c[2], c[3]);
            } else {
                __half h0, h1, l0, l1;
                split2h(c[0], h0, l0); split2h(c[1], h1, l1);
                *reinterpret_cast<__half2*>(&g_k_h[(size_t)m * D_DIM + n]) =
                    __halves2half2(h0, h1);
                *reinterpret_cast<__half2*>(&g_k_l[(size_t)m * D_DIM + n]) =
                    __halves2half2(l0, l1);
                split2h(c[2], h0, l0); split2h(c[3], h1, l1);
                *reinterpret_cast<__half2*>(&g_k_h[(size_t)(m + 8) * D_DIM + n]) =
                    __halves2half2(h0, h1);
                *reinterpret_cast<__half2*>(&g_k_l[(size_t)(m + 8) * D_DIM + n]) =
                    __halves2half2(l0, l1);
            }
        }
}

// ---------------------------------------------------------------------------
// c GEMM: c = (qh @ (kh+kl)^T)/256, triangular grid of 1056 live tiles.
// ---------------------------------------------------------------------------
__global__ __launch_bounds__(256, 3) void c_mma_kernel() {
    extern __shared__ Tiles stages[];   // [STAGES]

    const int bid = blockIdx.x;
    int by = (int)((sqrtf(4.0f * bid + 1.0f) - 1.0f) * 0.5f);
    while (by * by + by > bid) by--;
    while ((by + 1) * (by + 1) + (by + 1) <= bid) by++;
    const int bx = bid - (by * by + by);

    const int t0 = by * 128;
    const int j0 = bx * 64;

    const int tid  = threadIdx.x;
    const int warp = tid >> 5, lane = tid & 31;
    const int wm = warp >> 1, wn = warp & 1;
    const int g = lane >> 2, tg = lane & 3;

    float acc[2][4][4] = {};
    gemm_mainloop<D_DIM / 32>(
        stages, tid, wm, wn, lane,
        g_q_h + (size_t)t0 * D_DIM, D_DIM,
        g_k_h + (size_t)j0 * D_DIM, g_k_l + (size_t)j0 * D_DIM, D_DIM,
        acc);

    const float scale = 1.0f / 256.0f;
    #pragma unroll
    for (int ms = 0; ms < 2; ms++)
        #pragma unroll
        for (int ns = 0; ns < 4; ns++) {
            int m = t0 + wm * 32 + ms * 16 + g;
            int n = j0 + wn * 32 + ns * 8 + tg * 2;
            float* c = acc[ms][ns];
            *reinterpret_cast<float2*>(&g_c[(size_t)m * T_DIM + n]) =
                make_float2(c[0] * scale, c[1] * scale);
            *reinterpret_cast<float2*>(&g_c[(size_t)(m + 8) * T_DIM + n]) =
                make_float2(c[2] * scale, c[3] * scale);
        }
}

// ---------------------------------------------------------------------------
// scatter: each CTA owns (row t, vocab half). 64KB hist -> 3 CTAs/SM.
// (Reverted to the R6 configuration; the quarter-split regressed.)
// ---------------------------------------------------------------------------
#define HALF_V (VOCAB / 2)

__global__ __launch_bounds__(512) void scatter_kernel(float* __restrict__ out) {
    extern __shared__ float hist[];  // HALF_V floats = 64000 B
    const int t    = blockIdx.x >> 1;
    const int half = blockIdx.x & 1;
    const int vlo  = half * HALF_V;
    const int tid = threadIdx.x;
    const int nt = blockDim.x;

    float4* h4 = reinterpret_cast<float4*>(hist);
    const float4 z4 = make_float4(0.f, 0.f, 0.f, 0.f);
    for (int i = tid; i < HALF_V / 4; i += nt) h4[i] = z4;
    __syncthreads();

    const float* crow = &g_c[(size_t)t * T_DIM];
    for (int j = tid; j <= t; j += nt) {
        unsigned v = (unsigned)(g_idx[j] - vlo);
        if (v < (unsigned)HALF_V) atomicAdd(&hist[v], crow[j]);
    }
    __syncthreads();

    float4* o4 = reinterpret_cast<float4*>(out + (size_t)t * VOCAB + vlo);
    for (int i = tid; i < HALF_V / 4; i += nt) __stcs(&o4[i], h4[i]);
}

// ---------------------------------------------------------------------------
extern "C" void kernel_launch(void* const* d_in, const int* in_sizes, int n_in,
                              void* d_out, int out_size) {
    const float* x      = (const float*)d_in[0];
    const int*   idxraw = (const int*)d_in[1];
    const float* Wq     = (const float*)d_in[2];
    const float* Wk     = (const float*)d_in[3];
    float*       out    = (float*)d_out;
    (void)in_sizes; (void)n_in; (void)out_size;

    const int PIPE_SMEM = STAGES * (int)sizeof(Tiles);   // 61440 B

    idx_convert_kernel<<<1, 256>>>(idxraw);
    split_x_kernel<<<1024, 256>>>(x);
    split_w_kernel<<<dim3(64, 2), 256>>>(Wq, Wk);

    cudaFuncSetAttribute(qk_mma_kernel,
                         cudaFuncAttributeMaxDynamicSharedMemorySize, PIPE_SMEM);
    qk_mma_kernel<<<dim3(4, 32, 2), 256, PIPE_SMEM>>>();

    cudaFuncSetAttribute(c_mma_kernel,
                         cudaFuncAttributeMaxDynamicSharedMemorySize, PIPE_SMEM);
    c_mma_kernel<<<1056, 256, PIPE_SMEM>>>();

    cudaFuncSetAttribute(scatter_kernel,
                         cudaFuncAttributeMaxDynamicSharedMemorySize,
                         HALF_V * (int)sizeof(float));
    scatter_kernel<<<2 * T_DIM, 512, HALF_V * sizeof(float)>>>(out);
}

// round 11
// speedup vs baseline: 1.2976x; 1.0163x over previous
#include <cuda_runtime.h>
#include <cuda_fp16.h>
#include <cstdint>
#include <cstddef>

#define T_DIM 4096
#define C_DIM 1024
#define D_DIM 256
#define VOCAB 32000

// Shared tile row stride (fp16): 32 data + 8 pad = 40 (80B rows = 5*16B,
// uint4-aligned; ldmatrix phases conflict-free).
#define SMPAD 40
#define STAGES 3

// ---------------- scratch (__device__ globals: allocation-free rule) --------
// 2-term split-fp16 scheme: A operands hi-only, B operands hi+lo.
__device__ __half g_x_h[T_DIM * C_DIM];               // x hi (A of qk)
__device__ __half g_wt_h[2][D_DIM * C_DIM];           // W^T hi (B of qk)
__device__ __half g_wt_l[2][D_DIM * C_DIM];           // W^T lo
__device__ float  g_part[4][T_DIM * D_DIM];           // split-K partials
                                                      // z: 0=q/kh0 1=k/kh0 2=q/kh1 3=k/kh1
__device__ __half g_q_h[T_DIM * D_DIM];               // q hi (A of c)
__device__ __half g_k_h[T_DIM * D_DIM];               // k hi (B of c)
__device__ __half g_k_l[T_DIM * D_DIM];               // k lo
__device__ __half g_ch[(size_t)T_DIM * T_DIM];        // c in fp16, lower-tri only
__device__ int    g_idx[T_DIM];

// ---------------------------------------------------------------------------
__global__ void idx_convert_kernel(const int* __restrict__ raw) {
    __shared__ int is64;
    int tid = threadIdx.x;
    if (tid == 0) is64 = 1;
    __syncthreads();
    for (int i = tid; i < 1024; i += blockDim.x)
        if (raw[2 * i + 1] != 0) is64 = 0;
    __syncthreads();
    bool i64 = (is64 != 0);
    for (int i = tid; i < T_DIM; i += blockDim.x)
        g_idx[i] = i64 ? raw[2 * i] : raw[i];
}

__device__ __forceinline__ void split2h(float v, __half& h, __half& l) {
    h = __float2half_rn(v);
    l = __float2half_rn(v - __half2float(h));
}

__global__ void split_x_kernel(const float* __restrict__ x) {
    const int n4 = T_DIM * C_DIM / 4;
    __half2* H = reinterpret_cast<__half2*>(g_x_h);
    for (int i = blockIdx.x * blockDim.x + threadIdx.x; i < n4;
         i += gridDim.x * blockDim.x) {
        float4 v = reinterpret_cast<const float4*>(x)[i];
        H[2 * i]     = __floats2half2_rn(v.x, v.y);
        H[2 * i + 1] = __floats2half2_rn(v.z, v.w);
    }
}

__global__ void split_w_kernel(const float* __restrict__ Wq,
                               const float* __restrict__ Wk) {
    const float* W = blockIdx.y ? Wk : Wq;
    __half* hi = g_wt_h[blockIdx.y];
    __half* lo = g_wt_l[blockIdx.y];
    const int total = D_DIM * C_DIM;
    for (int i = blockIdx.x * blockDim.x + threadIdx.x; i < total;
         i += gridDim.x * blockDim.x) {
        int n = i / C_DIM, k = i % C_DIM;
        split2h(W[(size_t)k * D_DIM + n], hi[i], lo[i]);  // store transposed
    }
}

// ---------------------------------------------------------------------------
__device__ __forceinline__ void mma16816(float* d, const uint32_t* a,
                                         const uint32_t* b) {
    asm volatile(
        "mma.sync.aligned.m16n8k16.row.col.f32.f16.f16.f32 "
        "{%0,%1,%2,%3},{%4,%5,%6,%7},{%8,%9},{%0,%1,%2,%3};"
        : "+f"(d[0]), "+f"(d[1]), "+f"(d[2]), "+f"(d[3])
        : "r"(a[0]), "r"(a[1]), "r"(a[2]), "r"(a[3]), "r"(b[0]), "r"(b[1]));
}

__device__ __forceinline__ uint32_t smem_u32(const void* p) {
    return (uint32_t)__cvta_generic_to_shared(p);
}
__device__ __forceinline__ void ldsm4(uint32_t* r, const void* p) {
    asm volatile("ldmatrix.sync.aligned.m8n8.x4.shared.b16 {%0,%1,%2,%3}, [%4];"
                 : "=r"(r[0]), "=r"(r[1]), "=r"(r[2]), "=r"(r[3])
                 : "r"(smem_u32(p)));
}

__device__ __forceinline__ void cp16(void* smem, const void* gmem) {
    asm volatile("cp.async.cg.shared.global [%0], [%1], 16;"
                 :: "r"(smem_u32(smem)), "l"(gmem));
}
__device__ __forceinline__ void cp_commit() {
    asm volatile("cp.async.commit_group;");
}
template <int N>
__device__ __forceinline__ void cp_wait() {
    asm volatile("cp.async.wait_group %0;" :: "n"(N));
}

// One pipeline stage: 20480 B
struct Tiles {
    __half As_h[128][SMPAD];
    __half Bs_h[64][SMPAD];
    __half Bs_l[64][SMPAD];
};

// Compute one BK=32 slab. 8 warps (4x2), warp tile 32x32, 2-term split-fp16.
__device__ __forceinline__ void compute_slab(const Tiles& st, int wm, int wn,
                                             int lane, float acc[2][4][4]) {
    const int ra = (lane & 7) + ((lane >> 3) & 1) * 8;
    const int ca = (lane >> 4) * 8;
    const int rb = (lane & 7) + (lane >> 4) * 8;
    const int cb = ((lane >> 3) & 1) * 8;

    #pragma unroll
    for (int h = 0; h < 2; h++) {
        const int s16 = h * 16;
        uint32_t ah[2][4], bh[4][2], bl[4][2];
        #pragma unroll
        for (int ms = 0; ms < 2; ms++) {
            int r = wm * 32 + ms * 16 + ra;
            ldsm4(ah[ms], &st.As_h[r][s16 + ca]);
        }
        #pragma unroll
        for (int pr = 0; pr < 2; pr++) {
            int r = wn * 32 + pr * 16 + rb;
            uint32_t q[4];
            ldsm4(q, &st.Bs_h[r][s16 + cb]);
            bh[2 * pr][0] = q[0]; bh[2 * pr][1] = q[1];
            bh[2 * pr + 1][0] = q[2]; bh[2 * pr + 1][1] = q[3];
            ldsm4(q, &st.Bs_l[r][s16 + cb]);
            bl[2 * pr][0] = q[0]; bl[2 * pr][1] = q[1];
            bl[2 * pr + 1][0] = q[2]; bl[2 * pr + 1][1] = q[3];
        }
        #pragma unroll
        for (int ms = 0; ms < 2; ms++)
            #pragma unroll
            for (int ns = 0; ns < 4; ns++)
                mma16816(acc[ms][ns], ah[ms], bh[ns]);
        #pragma unroll
        for (int ms = 0; ms < 2; ms++)
            #pragma unroll
            for (int ns = 0; ns < 4; ns++)
                mma16816(acc[ms][ns], ah[ms], bl[ns]);
    }
}

__device__ __forceinline__ void load_slab(Tiles& st, int tid,
                                          const __half* a, size_t ldA,
                                          const __half* bH, const __half* bL,
                                          size_t ldB, int k0) {
    #pragma unroll
    for (int s = 0; s < 2; s++) {
        int idx = tid + s * 256;
        int r = idx >> 2, cw = (idx & 3) * 8;
        cp16(&st.As_h[r][cw], &a[(size_t)r * ldA + k0 + cw]);
    }
    {
        int r = tid >> 2, cw = (tid & 3) * 8;
        size_t go = (size_t)r * ldB + k0 + cw;
        cp16(&st.Bs_h[r][cw], &bH[go]);
        cp16(&st.Bs_l[r][cw], &bL[go]);
    }
    cp_commit();
}

template <int KT>
__device__ __forceinline__ void gemm_mainloop(
    Tiles* stages, int tid, int wm, int wn, int lane,
    const __half* a, size_t ldA,
    const __half* bH, const __half* bL, size_t ldB,
    float acc[2][4][4]) {

    load_slab(stages[0], tid, a, ldA, bH, bL, ldB, 0);
    if (KT > 1) load_slab(stages[1], tid, a, ldA, bH, bL, ldB, 32);

    for (int i = 0; i < KT; i++) {
        cp_wait<1>();
        __syncthreads();
        int nx = i + STAGES - 1;
        if (nx < KT)
            load_slab(stages[nx % STAGES], tid, a, ldA, bH, bL, ldB, nx * 32);
        else
            cp_commit();
        compute_slab(stages[i % STAGES], wm, wn, lane, acc);
    }
}

// ---------------------------------------------------------------------------
// qk GEMM, split-K x2: grid (4, 32, 4); z -> which = z&1 (0=q,1=k),
// khalf = z>>1 (K offset 0/512). Partials to g_part[z] (fp32).
// ---------------------------------------------------------------------------
__global__ __launch_bounds__(256, 3) void qk_mma_kernel() {
    extern __shared__ Tiles stages[];   // [STAGES]

    const int z = blockIdx.z;
    const int which = z & 1;
    const int koff = (z >> 1) * 512;
    const int m0 = blockIdx.y * 128;
    const int n0 = blockIdx.x * 64;

    const int tid  = threadIdx.x;
    const int warp = tid >> 5, lane = tid & 31;
    const int wm = warp >> 1, wn = warp & 1;
    const int g = lane >> 2, tg = lane & 3;

    float acc[2][4][4] = {};
    gemm_mainloop<16>(
        stages, tid, wm, wn, lane,
        g_x_h + (size_t)m0 * C_DIM + koff, C_DIM,
        g_wt_h[which] + (size_t)n0 * C_DIM + koff,
        g_wt_l[which] + (size_t)n0 * C_DIM + koff, C_DIM,
        acc);

    float* dst = g_part[z];
    #pragma unroll
    for (int ms = 0; ms < 2; ms++)
        #pragma unroll
        for (int ns = 0; ns < 4; ns++) {
            int m = m0 + wm * 32 + ms * 16 + g;
            int n = n0 + wn * 32 + ns * 8 + tg * 2;
            float* c = acc[ms][ns];
            *reinterpret_cast<float2*>(&dst[(size_t)m * D_DIM + n]) =
                make_float2(c[0], c[1]);
            *reinterpret_cast<float2*>(&dst[(size_t)(m + 8) * D_DIM + n]) =
                make_float2(c[2], c[3]);
        }
}

// Reduce split-K partials: q = p0+p2 (hi only), k = p1+p3 (hi+lo).
__global__ void qk_reduce_kernel() {
    const int n4 = T_DIM * D_DIM / 4;
    const float4* P0 = reinterpret_cast<const float4*>(g_part[0]);
    const float4* P1 = reinterpret_cast<const float4*>(g_part[1]);
    const float4* P2 = reinterpret_cast<const float4*>(g_part[2]);
    const float4* P3 = reinterpret_cast<const float4*>(g_part[3]);
    __half2* QH = reinterpret_cast<__half2*>(g_q_h);
    __half2* KH = reinterpret_cast<__half2*>(g_k_h);
    __half2* KL = reinterpret_cast<__half2*>(g_k_l);
    for (int i = blockIdx.x * blockDim.x + threadIdx.x; i < n4;
         i += gridDim.x * blockDim.x) {
        float4 a = P0[i], b = P2[i];
        QH[2 * i]     = __floats2half2_rn(a.x + b.x, a.y + b.y);
        QH[2 * i + 1] = __floats2half2_rn(a.z + b.z, a.w + b.w);
        a = P1[i]; b = P3[i];
        __half h0, l0, h1, l1;
        split2h(a.x + b.x, h0, l0); split2h(a.y + b.y, h1, l1);
        KH[2 * i] = __halves2half2(h0, h1);
        KL[2 * i] = __halves2half2(l0, l1);
        split2h(a.z + b.z, h0, l0); split2h(a.w + b.w, h1, l1);
        KH[2 * i + 1] = __halves2half2(h0, h1);
        KL[2 * i + 1] = __halves2half2(l0, l1);
    }
}

// ---------------------------------------------------------------------------
// c GEMM: c = (qh @ (kh+kl)^T)/256 -> fp16, triangular grid (1056 tiles).
// ---------------------------------------------------------------------------
__global__ __launch_bounds__(256, 3) void c_mma_kernel() {
    extern __shared__ Tiles stages[];   // [STAGES]

    const int bid = blockIdx.x;
    int by = (int)((sqrtf(4.0f * bid + 1.0f) - 1.0f) * 0.5f);
    while (by * by + by > bid) by--;
    while ((by + 1) * (by + 1) + (by + 1) <= bid) by++;
    const int bx = bid - (by * by + by);

    const int t0 = by * 128;
    const int j0 = bx * 64;

    const int tid  = threadIdx.x;
    const int warp = tid >> 5, lane = tid & 31;
    const int wm = warp >> 1, wn = warp & 1;
    const int g = lane >> 2, tg = lane & 3;

    float acc[2][4][4] = {};
    gemm_mainloop<D_DIM / 32>(
        stages, tid, wm, wn, lane,
        g_q_h + (size_t)t0 * D_DIM, D_DIM,
        g_k_h + (size_t)j0 * D_DIM, g_k_l + (size_t)j0 * D_DIM, D_DIM,
        acc);

    const float scale = 1.0f / 256.0f;
    #pragma unroll
    for (int ms = 0; ms < 2; ms++)
        #pragma unroll
        for (int ns = 0; ns < 4; ns++) {
            int m = t0 + wm * 32 + ms * 16 + g;
            int n = j0 + wn * 32 + ns * 8 + tg * 2;
            float* c = acc[ms][ns];
            *reinterpret_cast<__half2*>(&g_ch[(size_t)m * T_DIM + n]) =
                __floats2half2_rn(c[0] * scale, c[1] * scale);
            *reinterpret_cast<__half2*>(&g_ch[(size_t)(m + 8) * T_DIM + n]) =
                __floats2half2_rn(c[2] * scale, c[3] * scale);
        }
}

// ---------------------------------------------------------------------------
// scatter: each CTA owns (row t, vocab half). 64KB hist -> 3 CTAs/SM.
// ---------------------------------------------------------------------------
#define HALF_V (VOCAB / 2)

__global__ __launch_bounds__(512) void scatter_kernel(float* __restrict__ out) {
    extern __shared__ float hist[];  // HALF_V floats = 64000 B
    const int t    = blockIdx.x >> 1;
    const int half = blockIdx.x & 1;
    const int vlo  = half * HALF_V;
    const int tid = threadIdx.x;
    const int nt = blockDim.x;

    float4* h4 = reinterpret_cast<float4*>(hist);
    const float4 z4 = make_float4(0.f, 0.f, 0.f, 0.f);
    for (int i = tid; i < HALF_V / 4; i += nt) h4[i] = z4;
    __syncthreads();

    const __half* crow = &g_ch[(size_t)t * T_DIM];
    for (int j = tid; j <= t; j += nt) {
        unsigned v = (unsigned)(g_idx[j] - vlo);
        if (v < (unsigned)HALF_V) atomicAdd(&hist[v], __half2float(crow[j]));
    }
    __syncthreads();

    float4* o4 = reinterpret_cast<float4*>(out + (size_t)t * VOCAB + vlo);
    for (int i = tid; i < HALF_V / 4; i += nt) __stcs(&o4[i], h4[i]);
}

// ---------------------------------------------------------------------------
extern "C" void kernel_launch(void* const* d_in, const int* in_sizes, int n_in,
                              void* d_out, int out_size) {
    const float* x      = (const float*)d_in[0];
    const int*   idxraw = (const int*)d_in[1];
    const float* Wq     = (const float*)d_in[2];
    const float* Wk     = (const float*)d_in[3];
    float*       out    = (float*)d_out;
    (void)in_sizes; (void)n_in; (void)out_size;

    const int PIPE_SMEM = STAGES * (int)sizeof(Tiles);   // 61440 B

    idx_convert_kernel<<<1, 256>>>(idxraw);
    split_x_kernel<<<1024, 256>>>(x);
    split_w_kernel<<<dim3(64, 2), 256>>>(Wq, Wk);

    cudaFuncSetAttribute(qk_mma_kernel,
                         cudaFuncAttributeMaxDynamicSharedMemorySize, PIPE_SMEM);
    qk_mma_kernel<<<dim3(4, 32, 4), 256, PIPE_SMEM>>>();

    qk_reduce_kernel<<<512, 256>>>();

    cudaFuncSetAttribute(c_mma_kernel,
                         cudaFuncAttributeMaxDynamicSharedMemorySize, PIPE_SMEM);
    c_mma_kernel<<<1056, 256, PIPE_SMEM>>>();

    cudaFuncSetAttribute(scatter_kernel,
                         cudaFuncAttributeMaxDynamicSharedMemorySize,
                         HALF_V * (int)sizeof(float));
    scatter_kernel<<<2 * T_DIM, 512, HALF_V * sizeof(float)>>>(out);
}

// round 12
// speedup vs baseline: 1.4273x; 1.0999x over previous
#include <cuda_runtime.h>
#include <cuda_fp16.h>
#include <cstdint>
#include <cstddef>

#define T_DIM 4096
#define C_DIM 1024
#define D_DIM 256
#define VOCAB 32000

// Shared tile row stride (fp16): 32 data + 8 pad = 40 (80B rows = 5*16B,
// uint4-aligned; ldmatrix phases conflict-free).
#define SMPAD 40
#define STAGES 3

// ---------------- scratch (__device__ globals: allocation-free rule) --------
// Full 1-term fp16 pipeline (validated error model: ~5.4e-4 total).
__device__ __half g_x_h[T_DIM * C_DIM];               // x fp16
__device__ __half g_wt_h[2][D_DIM * C_DIM];           // W^T fp16, 0=Wq 1=Wk
__device__ float  g_part[4][T_DIM * D_DIM];           // split-K partials
                                                      // z: 0=q/kh0 1=k/kh0 2=q/kh1 3=k/kh1
__device__ __half g_q_h[T_DIM * D_DIM];               // q fp16
__device__ __half g_k_h[T_DIM * D_DIM];               // k fp16
__device__ __half g_ch[(size_t)T_DIM * T_DIM];        // c fp16, lower-tri only
__device__ int    g_idx[T_DIM];

// ---------------------------------------------------------------------------
__global__ void idx_convert_kernel(const int* __restrict__ raw) {
    __shared__ int is64;
    int tid = threadIdx.x;
    if (tid == 0) is64 = 1;
    __syncthreads();
    for (int i = tid; i < 1024; i += blockDim.x)
        if (raw[2 * i + 1] != 0) is64 = 0;
    __syncthreads();
    bool i64 = (is64 != 0);
    for (int i = tid; i < T_DIM; i += blockDim.x)
        g_idx[i] = i64 ? raw[2 * i] : raw[i];
}

__global__ void split_x_kernel(const float* __restrict__ x) {
    const int n4 = T_DIM * C_DIM / 4;
    __half2* H = reinterpret_cast<__half2*>(g_x_h);
    for (int i = blockIdx.x * blockDim.x + threadIdx.x; i < n4;
         i += gridDim.x * blockDim.x) {
        float4 v = reinterpret_cast<const float4*>(x)[i];
        H[2 * i]     = __floats2half2_rn(v.x, v.y);
        H[2 * i + 1] = __floats2half2_rn(v.z, v.w);
    }
}

__global__ void split_w_kernel(const float* __restrict__ Wq,
                               const float* __restrict__ Wk) {
    const float* W = blockIdx.y ? Wk : Wq;
    __half* hi = g_wt_h[blockIdx.y];
    const int total = D_DIM * C_DIM;
    for (int i = blockIdx.x * blockDim.x + threadIdx.x; i < total;
         i += gridDim.x * blockDim.x) {
        int n = i / C_DIM, k = i % C_DIM;
        hi[i] = __float2half_rn(W[(size_t)k * D_DIM + n]);  // store transposed
    }
}

// ---------------------------------------------------------------------------
__device__ __forceinline__ void mma16816(float* d, const uint32_t* a,
                                         const uint32_t* b) {
    asm volatile(
        "mma.sync.aligned.m16n8k16.row.col.f32.f16.f16.f32 "
        "{%0,%1,%2,%3},{%4,%5,%6,%7},{%8,%9},{%0,%1,%2,%3};"
        : "+f"(d[0]), "+f"(d[1]), "+f"(d[2]), "+f"(d[3])
        : "r"(a[0]), "r"(a[1]), "r"(a[2]), "r"(a[3]), "r"(b[0]), "r"(b[1]));
}

__device__ __forceinline__ uint32_t smem_u32(const void* p) {
    return (uint32_t)__cvta_generic_to_shared(p);
}
__device__ __forceinline__ void ldsm4(uint32_t* r, const void* p) {
    asm volatile("ldmatrix.sync.aligned.m8n8.x4.shared.b16 {%0,%1,%2,%3}, [%4];"
                 : "=r"(r[0]), "=r"(r[1]), "=r"(r[2]), "=r"(r[3])
                 : "r"(smem_u32(p)));
}

__device__ __forceinline__ void cp16(void* smem, const void* gmem) {
    asm volatile("cp.async.cg.shared.global [%0], [%1], 16;"
                 :: "r"(smem_u32(smem)), "l"(gmem));
}
__device__ __forceinline__ void cp_commit() {
    asm volatile("cp.async.commit_group;");
}
template <int N>
__device__ __forceinline__ void cp_wait() {
    asm volatile("cp.async.wait_group %0;" :: "n"(N));
}

// One pipeline stage: 15360 B (A 10240, B 5120)
struct Tiles {
    __half As_h[128][SMPAD];
    __half Bs_h[64][SMPAD];
};

// Compute one BK=32 slab. 8 warps (4x2), warp tile 32x32, single-term fp16:
// per k16 half: 4 LDSM.x4 -> 8 HMMA; 8 LDSM + 16 HMMA per slab.
__device__ __forceinline__ void compute_slab(const Tiles& st, int wm, int wn,
                                             int lane, float acc[2][4][4]) {
    const int ra = (lane & 7) + ((lane >> 3) & 1) * 8;
    const int ca = (lane >> 4) * 8;
    const int rb = (lane & 7) + (lane >> 4) * 8;
    const int cb = ((lane >> 3) & 1) * 8;

    #pragma unroll
    for (int h = 0; h < 2; h++) {
        const int s16 = h * 16;
        uint32_t ah[2][4], bh[4][2];
        #pragma unroll
        for (int ms = 0; ms < 2; ms++) {
            int r = wm * 32 + ms * 16 + ra;
            ldsm4(ah[ms], &st.As_h[r][s16 + ca]);
        }
        #pragma unroll
        for (int pr = 0; pr < 2; pr++) {
            int r = wn * 32 + pr * 16 + rb;
            uint32_t q[4];
            ldsm4(q, &st.Bs_h[r][s16 + cb]);
            bh[2 * pr][0] = q[0]; bh[2 * pr][1] = q[1];
            bh[2 * pr + 1][0] = q[2]; bh[2 * pr + 1][1] = q[3];
        }
        #pragma unroll
        for (int ms = 0; ms < 2; ms++)
            #pragma unroll
            for (int ns = 0; ns < 4; ns++)
                mma16816(acc[ms][ns], ah[ms], bh[ns]);
    }
}

// Async-load one slab (3 cp16 per thread) and commit one group.
__device__ __forceinline__ void load_slab(Tiles& st, int tid,
                                          const __half* a, size_t ldA,
                                          const __half* bH, size_t ldB,
                                          int k0) {
    #pragma unroll
    for (int s = 0; s < 2; s++) {
        int idx = tid + s * 256;
        int r = idx >> 2, cw = (idx & 3) * 8;
        cp16(&st.As_h[r][cw], &a[(size_t)r * ldA + k0 + cw]);
    }
    {
        int r = tid >> 2, cw = (tid & 3) * 8;
        cp16(&st.Bs_h[r][cw], &bH[(size_t)r * ldB + k0 + cw]);
    }
    cp_commit();
}

// 3-stage, single-sync-per-slab mainloop.
template <int KT>
__device__ __forceinline__ void gemm_mainloop(
    Tiles* stages, int tid, int wm, int wn, int lane,
    const __half* a, size_t ldA, const __half* bH, size_t ldB,
    float acc[2][4][4]) {

    load_slab(stages[0], tid, a, ldA, bH, ldB, 0);
    if (KT > 1) load_slab(stages[1], tid, a, ldA, bH, ldB, 32);

    for (int i = 0; i < KT; i++) {
        cp_wait<1>();
        __syncthreads();
        int nx = i + STAGES - 1;
        if (nx < KT)
            load_slab(stages[nx % STAGES], tid, a, ldA, bH, ldB, nx * 32);
        else
            cp_commit();
        compute_slab(stages[i % STAGES], wm, wn, lane, acc);
    }
}

// ---------------------------------------------------------------------------
// qk GEMM, split-K x2: grid (4, 32, 4); which = z&1 (0=q,1=k),
// K offset = (z>>1)*512. Partials to g_part[z] (fp32).
// ---------------------------------------------------------------------------
__global__ __launch_bounds__(256, 4) void qk_mma_kernel() {
    extern __shared__ Tiles stages[];   // [STAGES]

    const int z = blockIdx.z;
    const int which = z & 1;
    const int koff = (z >> 1) * 512;
    const int m0 = blockIdx.y * 128;
    const int n0 = blockIdx.x * 64;

    const int tid  = threadIdx.x;
    const int warp = tid >> 5, lane = tid & 31;
    const int wm = warp >> 1, wn = warp & 1;
    const int g = lane >> 2, tg = lane & 3;

    float acc[2][4][4] = {};
    gemm_mainloop<16>(
        stages, tid, wm, wn, lane,
        g_x_h + (size_t)m0 * C_DIM + koff, C_DIM,
        g_wt_h[which] + (size_t)n0 * C_DIM + koff, C_DIM,
        acc);

    float* dst = g_part[z];
    #pragma unroll
    for (int ms = 0; ms < 2; ms++)
        #pragma unroll
        for (int ns = 0; ns < 4; ns++) {
            int m = m0 + wm * 32 + ms * 16 + g;
            int n = n0 + wn * 32 + ns * 8 + tg * 2;
            float* c = acc[ms][ns];
            *reinterpret_cast<float2*>(&dst[(size_t)m * D_DIM + n]) =
                make_float2(c[0], c[1]);
            *reinterpret_cast<float2*>(&dst[(size_t)(m + 8) * D_DIM + n]) =
                make_float2(c[2], c[3]);
        }
}

// Reduce split-K partials: q = p0+p2, k = p1+p3 (both to single fp16).
__global__ void qk_reduce_kernel() {
    const int n4 = T_DIM * D_DIM / 4;
    const float4* P0 = reinterpret_cast<const float4*>(g_part[0]);
    const float4* P1 = reinterpret_cast<const float4*>(g_part[1]);
    const float4* P2 = reinterpret_cast<const float4*>(g_part[2]);
    const float4* P3 = reinterpret_cast<const float4*>(g_part[3]);
    __half2* QH = reinterpret_cast<__half2*>(g_q_h);
    __half2* KH = reinterpret_cast<__half2*>(g_k_h);
    for (int i = blockIdx.x * blockDim.x + threadIdx.x; i < n4;
         i += gridDim.x * blockDim.x) {
        float4 a = P0[i], b = P2[i];
        QH[2 * i]     = __floats2half2_rn(a.x + b.x, a.y + b.y);
        QH[2 * i + 1] = __floats2half2_rn(a.z + b.z, a.w + b.w);
        a = P1[i]; b = P3[i];
        KH[2 * i]     = __floats2half2_rn(a.x + b.x, a.y + b.y);
        KH[2 * i + 1] = __floats2half2_rn(a.z + b.z, a.w + b.w);
    }
}

// ---------------------------------------------------------------------------
// c GEMM: c = (qh @ kh^T)/256 -> fp16, triangular grid (1056 live tiles).
// ---------------------------------------------------------------------------
__global__ __launch_bounds__(256, 4) void c_mma_kernel() {
    extern __shared__ Tiles stages[];   // [STAGES]

    const int bid = blockIdx.x;
    int by = (int)((sqrtf(4.0f * bid + 1.0f) - 1.0f) * 0.5f);
    while (by * by + by > bid) by--;
    while ((by + 1) * (by + 1) + (by + 1) <= bid) by++;
    const int bx = bid - (by * by + by);

    const int t0 = by * 128;
    const int j0 = bx * 64;

    const int tid  = threadIdx.x;
    const int warp = tid >> 5, lane = tid & 31;
    const int wm = warp >> 1, wn = warp & 1;
    const int g = lane >> 2, tg = lane & 3;

    float acc[2][4][4] = {};
    gemm_mainloop<D_DIM / 32>(
        stages, tid, wm, wn, lane,
        g_q_h + (size_t)t0 * D_DIM, D_DIM,
        g_k_h + (size_t)j0 * D_DIM, D_DIM,
        acc);

    const float scale = 1.0f / 256.0f;
    #pragma unroll
    for (int ms = 0; ms < 2; ms++)
        #pragma unroll
        for (int ns = 0; ns < 4; ns++) {
            int m = t0 + wm * 32 + ms * 16 + g;
            int n = j0 + wn * 32 + ns * 8 + tg * 2;
            float* c = acc[ms][ns];
            *reinterpret_cast<__half2*>(&g_ch[(size_t)m * T_DIM + n]) =
                __floats2half2_rn(c[0] * scale, c[1] * scale);
            *reinterpret_cast<__half2*>(&g_ch[(size_t)(m + 8) * T_DIM + n]) =
                __floats2half2_rn(c[2] * scale, c[3] * scale);
        }
}

// ---------------------------------------------------------------------------
// scatter: each CTA owns (row t, vocab half). 64KB hist -> 3 CTAs/SM.
// ---------------------------------------------------------------------------
#define HALF_V (VOCAB / 2)

__global__ __launch_bounds__(512) void scatter_kernel(float* __restrict__ out) {
    extern __shared__ float hist[];  // HALF_V floats = 64000 B
    const int t    = blockIdx.x >> 1;
    const int half = blockIdx.x & 1;
    const int vlo  = half * HALF_V;
    const int tid = threadIdx.x;
    const int nt = blockDim.x;

    float4* h4 = reinterpret_cast<float4*>(hist);
    const float4 z4 = make_float4(0.f, 0.f, 0.f, 0.f);
    for (int i = tid; i < HALF_V / 4; i += nt) h4[i] = z4;
    __syncthreads();

    const __half* crow = &g_ch[(size_t)t * T_DIM];
    for (int j = tid; j <= t; j += nt) {
        unsigned v = (unsigned)(g_idx[j] - vlo);
        if (v < (unsigned)HALF_V) atomicAdd(&hist[v], __half2float(crow[j]));
    }
    __syncthreads();

    float4* o4 = reinterpret_cast<float4*>(out + (size_t)t * VOCAB + vlo);
    for (int i = tid; i < HALF_V / 4; i += nt) __stcs(&o4[i], h4[i]);
}

// ---------------------------------------------------------------------------
extern "C" void kernel_launch(void* const* d_in, const int* in_sizes, int n_in,
                              void* d_out, int out_size) {
    const float* x      = (const float*)d_in[0];
    const int*   idxraw = (const int*)d_in[1];
    const float* Wq     = (const float*)d_in[2];
    const float* Wk     = (const float*)d_in[3];
    float*       out    = (float*)d_out;
    (void)in_sizes; (void)n_in; (void)out_size;

    const int PIPE_SMEM = STAGES * (int)sizeof(Tiles);   // 46080 B

    idx_convert_kernel<<<1, 256>>>(idxraw);
    split_x_kernel<<<1024, 256>>>(x);
    split_w_kernel<<<dim3(64, 2), 256>>>(Wq, Wk);

    cudaFuncSetAttribute(qk_mma_kernel,
                         cudaFuncAttributeMaxDynamicSharedMemorySize, PIPE_SMEM);
    qk_mma_kernel<<<dim3(4, 32, 4), 256, PIPE_SMEM>>>();

    qk_reduce_kernel<<<512, 256>>>();

    cudaFuncSetAttribute(c_mma_kernel,
                         cudaFuncAttributeMaxDynamicSharedMemorySize, PIPE_SMEM);
    c_mma_kernel<<<1056, 256, PIPE_SMEM>>>();

    cudaFuncSetAttribute(scatter_kernel,
                         cudaFuncAttributeMaxDynamicSharedMemorySize,
                         HALF_V * (int)sizeof(float));
    scatter_kernel<<<2 * T_DIM, 512, HALF_V * sizeof(float)>>>(out);
}